// round 12
// baseline (speedup 1.0000x reference)
#include <cuda_runtime.h>
#include <cuda_fp16.h>
#include <cstdint>

#define BI 128
#define BT 128
#define RR 36
#define WW 50
#define DD 256
#define ILAMB 20.0f     // 1/0.05
#define EPSV 1e-6f

#define IP 2            // imgs per block
#define JP 4            // caps per block
#define NPAIR 8         // IP*JP
#define KC 32           // K-chunk (2 x k16 mma steps)
#define NCHUNK (DD / KC)   // 8
#define MT 3            // 48 rows padded
#define NT 7            // 56 cols padded
#define NKS (KC / 16)   // 2 k-steps per chunk
#define NKS_TOT (DD / 16)  // 16 global k-steps

// Pre-baked fp16 fragment layouts in gmem (u32 = f16x2), ks-major:
// A quad (4xu32/lane) at ((ksg*3+mt)*32 + lane): {a0,a1,a2,a3} of m16n8k16
// B pair (2xu32/lane) at ((ksg*7+nt)*32 + lane): {b0,b1}
#define A_IMG_U32 (NKS_TOT * MT * 128)   // 6144 per image
#define B_CAP_U32 (NKS_TOT * NT * 64)    // 7168 per cap
#define A_CHUNK_U32 (NKS * MT * 128)     // 768 per image per chunk
#define B_CHUNK_U32 (NKS * NT * 64)      // 896 per cap per chunk
#define A_REG_U32 (IP * A_CHUNK_U32)     // 1536
#define B_REG_U32 (JP * B_CHUNK_U32)     // 3584
#define BUF_U32 (A_REG_U32 + B_REG_U32)  // 5120
#define BUF_BYTES (BUF_U32 * 4)          // 20480
#define NBUF 4

// Sinkhorn scratch (fp32; reuses the staging buffers after GEMM)
#define KW 58                           // even: float2 row dots; col walk bijective
#define KS_STRIDE (RR * KW)             // 2088
#define AL_OFF (NPAIR * KS_STRIDE)      // 16704
#define BE_OFF (AL_OFF + NPAIR * RR)    // 16992
#define BET_STRIDE 52                   // WW + pad (float2 tail reads zeros)

#define SMEM_U32 (NBUF * BUF_U32)       // 20480 (> 17408 Sinkhorn floats)
#define SMEM_BYTES (SMEM_U32 * 4)       // 81920

#define NORM_SMEM_BYTES (B_CAP_U32 * 4) // 28672 (max of A/B block)

__device__ uint32_t g_aq[BI * A_IMG_U32];
__device__ uint32_t g_bq[BT * B_CAP_U32];

__device__ __forceinline__ uint32_t pack_h2(float lo, float hi) {
    uint32_t r;
    asm("cvt.rn.f16x2.f32 %0, %1, %2;" : "=r"(r) : "f"(hi), "f"(lo));
    return r;
}

__device__ __forceinline__ void cp16(uint32_t dst, const void* src) {
    asm volatile("cp.async.cg.shared.global [%0], [%1], 16;\n"
                 :: "r"(dst), "l"(src));
}

// ---------------------------------------------------------------------------
// Kernel 1: L2-normalize, convert to fp16 pairs, build fragment layout in
// smem, dump coalesced. One block per image (b < BI) or cap (b >= BI).
// Lane L owns k-octet 8L..8L+7: ksg = L>>1, sel = L&1 (k-offset 8*sel).
// ---------------------------------------------------------------------------
__global__ __launch_bounds__(256)
void norm_kernel(const float* __restrict__ imgs,
                 const float* __restrict__ caps) {
    extern __shared__ uint32_t sm[];
    const int b = blockIdx.x;
    const int tid = threadIdx.x;
    const int lane = tid & 31;
    const int wrp = tid >> 5;
    const int ksg = lane >> 1;
    const int sel = lane & 1;

    if (b < BI) {
        for (int r = wrp; r < 48; r += 8) {
            float v[8];
            if (r < RR) {
                const float4* s4 = reinterpret_cast<const float4*>(
                    imgs + ((size_t)b * RR + r) * DD);
                float4 v0 = s4[2 * lane], v1 = s4[2 * lane + 1];
                float ss = v0.x * v0.x + v0.y * v0.y + v0.z * v0.z + v0.w * v0.w
                         + v1.x * v1.x + v1.y * v1.y + v1.z * v1.z + v1.w * v1.w;
#pragma unroll
                for (int o = 16; o > 0; o >>= 1)
                    ss += __shfl_xor_sync(0xffffffffu, ss, o);
                float inv = 1.0f / fmaxf(sqrtf(ss), 1e-8f);
                v[0] = v0.x * inv; v[1] = v0.y * inv;
                v[2] = v0.z * inv; v[3] = v0.w * inv;
                v[4] = v1.x * inv; v[5] = v1.y * inv;
                v[6] = v1.z * inv; v[7] = v1.w * inv;
            } else {
#pragma unroll
                for (int y = 0; y < 8; ++y) v[y] = 0.0f;
            }
            int mt = r >> 4, x = r & 15, g = x & 7, hi = x >> 3;
#pragma unroll
            for (int t = 0; t < 4; ++t) {
                sm[((ksg * 3 + mt) * 32 + g * 4 + t) * 4 + sel * 2 + hi] =
                    pack_h2(v[2 * t], v[2 * t + 1]);
            }
        }
        __syncthreads();
        uint4* dst = reinterpret_cast<uint4*>(g_aq + (size_t)b * A_IMG_U32);
        const uint4* src = reinterpret_cast<const uint4*>(sm);
#pragma unroll
        for (int s = 0; s < A_IMG_U32 / 4 / 256; ++s)
            dst[tid + s * 256] = src[tid + s * 256];
    } else {
        const int j = b - BI;
        for (int w = wrp; w < 56; w += 8) {
            float v[8];
            if (w < WW) {
                const float4* s4 = reinterpret_cast<const float4*>(
                    caps + ((size_t)j * WW + w) * DD);
                float4 v0 = s4[2 * lane], v1 = s4[2 * lane + 1];
                float ss = v0.x * v0.x + v0.y * v0.y + v0.z * v0.z + v0.w * v0.w
                         + v1.x * v1.x + v1.y * v1.y + v1.z * v1.z + v1.w * v1.w;
#pragma unroll
                for (int o = 16; o > 0; o >>= 1)
                    ss += __shfl_xor_sync(0xffffffffu, ss, o);
                float inv = 1.0f / fmaxf(sqrtf(ss), 1e-8f);
                v[0] = v0.x * inv; v[1] = v0.y * inv;
                v[2] = v0.z * inv; v[3] = v0.w * inv;
                v[4] = v1.x * inv; v[5] = v1.y * inv;
                v[6] = v1.z * inv; v[7] = v1.w * inv;
            } else {
#pragma unroll
                for (int y = 0; y < 8; ++y) v[y] = 0.0f;
            }
            int nt = w >> 3, g = w & 7;
#pragma unroll
            for (int t = 0; t < 4; ++t) {
                sm[((ksg * 7 + nt) * 32 + g * 4 + t) * 2 + sel] =
                    pack_h2(v[2 * t], v[2 * t + 1]);
            }
        }
        __syncthreads();
        uint4* dst = reinterpret_cast<uint4*>(g_bq + (size_t)j * B_CAP_U32);
        const uint4* src = reinterpret_cast<const uint4*>(sm);
#pragma unroll
        for (int s = 0; s < B_CAP_U32 / 4 / 256; ++s)
            dst[tid + s * 256] = src[tid + s * 256];
    }
}

// ---------------------------------------------------------------------------
// m16n8k16 fp16 mma, fp32 accumulate
// ---------------------------------------------------------------------------
__device__ __forceinline__ void mma_f16(float* c, const uint4& a, const uint2& b) {
    asm volatile(
        "mma.sync.aligned.m16n8k16.row.col.f32.f16.f16.f32 "
        "{%0,%1,%2,%3}, {%4,%5,%6,%7}, {%8,%9}, {%0,%1,%2,%3};\n"
        : "+f"(c[0]), "+f"(c[1]), "+f"(c[2]), "+f"(c[3])
        : "r"(a.x), "r"(a.y), "r"(a.z), "r"(a.w), "r"(b.x), "r"(b.y));
}

// ---------------------------------------------------------------------------
// Kernel 2: fused GEMM (fp16 mma.sync, 4-buffer cp.async pipeline, prefetch
// distance 2, ONE barrier per chunk) + Sinkhorn.
// Block = IP imgs x JP caps; warp w owns pair (ii = w>>2, jj = w&3).
// ---------------------------------------------------------------------------
__global__ __launch_bounds__(256, 2)
void wass_kernel(const int* __restrict__ img_lens,
                 const int* __restrict__ cap_lens,
                 float* __restrict__ out) {
    extern __shared__ float smem[];
    uint32_t* sm32 = reinterpret_cast<uint32_t*>(smem);
    const int i0 = blockIdx.y * IP;
    const int j0 = blockIdx.x * JP;
    const int tid = threadIdx.x;
    const int lane = tid & 31;
    const int wid = tid >> 5;
    const int gid = lane >> 2;
    const int tig = lane & 3;
    const int ii = wid >> 2;
    const int jj = wid & 3;

    uint32_t sb;
    asm("{ .reg .u64 t; cvta.to.shared.u64 t, %1; cvt.u32.u64 %0, t; }"
        : "=r"(sb) : "l"(smem));

    // --- per-thread staging assignment (constant; src advances per chunk) ---
    // A: 384 quads/chunk. q0 = tid (img = tid>=192); q1 = 256+tid for tid<128
    //    (always img1, at constant offset +6400 u32 / +4096 B from q0).
    // B: 64 threads per cap, quads tB, tB+64, tB+128, (+192 if tB<32).
    const int imA = (tid >= 192) ? 1 : 0;
    const int posA = tid - imA * 192;
    const uint32_t* srcA = g_aq + (size_t)(i0 + imA) * A_IMG_U32 + posA * 4;
    const uint32_t dstA = (uint32_t)(imA * 3072 + posA * 16);
    const int capB = tid >> 6, tB = tid & 63;
    const uint32_t* srcB = g_bq + (size_t)(j0 + capB) * B_CAP_U32 + tB * 4;
    const uint32_t dstB = (uint32_t)(6144 + capB * 3584 + tB * 16);
    const bool a2 = (tid < 128);
    const bool b4 = (tB < 32);

    float C[MT][NT][4];
#pragma unroll
    for (int mt = 0; mt < MT; ++mt)
#pragma unroll
        for (int nt = 0; nt < NT; ++nt)
#pragma unroll
            for (int c = 0; c < 4; ++c) C[mt][nt][c] = 0.0f;

    auto do_stage = [&](int s) {
        uint32_t bufb = sb + (uint32_t)(s & (NBUF - 1)) * BUF_BYTES;
        cp16(bufb + dstA, srcA);
        if (a2) cp16(bufb + dstA + 4096, srcA + 6400);
        cp16(bufb + dstB, srcB);
        cp16(bufb + dstB + 1024, srcB + 256);
        cp16(bufb + dstB + 2048, srcB + 512);
        if (b4) cp16(bufb + dstB + 3072, srcB + 768);
        srcA += A_CHUNK_U32;
        srcB += B_CHUNK_U32;
        asm volatile("cp.async.commit_group;" ::: "memory");
    };

    // prologue: chunks 0 and 1 in flight
    do_stage(0);
    do_stage(1);

    for (int ch = 0; ch < NCHUNK; ++ch) {
        if (ch < NCHUNK - 1) {
            asm volatile("cp.async.wait_group 1;" ::: "memory");
        } else {
            asm volatile("cp.async.wait_group 0;" ::: "memory");
        }
        __syncthreads();            // single barrier per chunk
        if (ch + 2 < NCHUNK) do_stage(ch + 2);

        const uint32_t* buf = sm32 + (ch & (NBUF - 1)) * BUF_U32;
        const uint4* Aq = reinterpret_cast<const uint4*>(buf)
                        + ii * (A_CHUNK_U32 / 4);
        const uint2* Bq = reinterpret_cast<const uint2*>(buf + A_REG_U32)
                        + jj * (B_CHUNK_U32 / 2);
#pragma unroll
        for (int ks = 0; ks < NKS; ++ks) {
            uint4 a[MT];
#pragma unroll
            for (int mt = 0; mt < MT; ++mt)
                a[mt] = Aq[(ks * 3 + mt) * 32 + lane];       // one LDS.128
#pragma unroll
            for (int nt = 0; nt < NT; ++nt) {
                uint2 b = Bq[(ks * 7 + nt) * 32 + lane];     // one LDS.64
#pragma unroll
                for (int mt = 0; mt < MT; ++mt) mma_f16(C[mt][nt], a[mt], b);
            }
        }
    }
    __syncthreads();   // all compute done; staging region reused for Sinkhorn

    // ---------------- Sinkhorn (warp-private per pair) ----------------
    const int i = i0 + ii;
    const int j = j0 + jj;
    const int Ri = img_lens[i];
    const int Wj = cap_lens[j];
    float* Kp = smem + wid * KS_STRIDE;           // [36][58]
    float* alp = smem + AL_OFF + wid * RR;        // [36]
    float* bet = smem + BE_OFF + wid * BET_STRIDE; // [52]

    // K = exp((s-1)/lambda) masked; accumulate total sum.
    // Ri/Wj warp-uniform: tile guards are uniform branches.
    float tsum = 0.0f;
#pragma unroll
    for (int mt = 0; mt < MT; ++mt) {
        if (mt * 16 < Ri) {
#pragma unroll
            for (int nt = 0; nt < NT; ++nt) {
                if (nt * 8 < Wj) {
#pragma unroll
                    for (int c = 0; c < 4; ++c) {
                        int r = mt * 16 + gid + ((c >> 1) << 3);
                        int w = nt * 8 + (tig << 1) + (c & 1);
                        if (r < Ri && w < Wj) {
                            float s = C[mt][nt][c];
                            float k = __expf(ILAMB * s - ILAMB);
                            Kp[r * KW + w] = k;
                            tsum += k;
                        }
                    }
                }
            }
        }
    }
#pragma unroll
    for (int o = 16; o > 0; o >>= 1) tsum += __shfl_xor_sync(0xffffffffu, tsum, o);
    float alpha0 = 1.0f / (tsum + EPSV);

    for (int r = lane; r < Ri; r += 32) alp[r] = alpha0;
    // bet with zeroed pad element (odd Wj) so float2 row-dot tails read zeros
    for (int w = lane; w < Wj + (Wj & 1); w += 32)
        bet[w] = (w < Wj) ? 1.0f : 0.0f;
    if (Wj & 1)
        for (int r = lane; r < Ri; r += 32) Kp[r * KW + Wj] = 0.0f;
    const float rm = 1.0f / (float)Ri;
    const float cm = 1.0f / (float)Wj;
    __syncwarp();

    const int nh = (Wj + 1) >> 1;
#pragma unroll
    for (int it = 0; it < 3; ++it) {
        for (int r = lane; r < Ri; r += 32) {
            const float2* kr = reinterpret_cast<const float2*>(Kp + r * KW);
            const float2* b2 = reinterpret_cast<const float2*>(bet);
            float dot = 0.0f;
            for (int t = 0; t < nh; ++t) {
                float2 kv = kr[t], bv = b2[t];
                dot += kv.x * bv.x;
                dot += kv.y * bv.y;
            }
            float a = alp[r];
            alp[r] = a * (rm / (a * dot + EPSV));
        }
        __syncwarp();
        for (int w = lane; w < Wj; w += 32) {
            float dot = 0.0f;
            for (int r = 0; r < Ri; ++r) dot += Kp[r * KW + w] * alp[r];
            float b = bet[w];
            bet[w] = b * (cm / (b * dot + EPSV));
        }
        __syncwarp();
    }

    // final: sum s * K * alpha_r * beta_w; K re-read from smem (bit-identical)
    float acc = 0.0f;
#pragma unroll
    for (int mt = 0; mt < MT; ++mt) {
        if (mt * 16 < Ri) {
#pragma unroll
            for (int nt = 0; nt < NT; ++nt) {
                if (nt * 8 < Wj) {
#pragma unroll
                    for (int c = 0; c < 4; ++c) {
                        int r = mt * 16 + gid + ((c >> 1) << 3);
                        int w = nt * 8 + (tig << 1) + (c & 1);
                        if (r < Ri && w < Wj) {
                            float s = C[mt][nt][c];
                            float k = Kp[r * KW + w];
                            acc += s * k * alp[r] * bet[w];
                        }
                    }
                }
            }
        }
    }
#pragma unroll
    for (int o = 16; o > 0; o >>= 1) acc += __shfl_xor_sync(0xffffffffu, acc, o);
    if (lane == 0) out[i * BT + j] = acc;
}

// ---------------------------------------------------------------------------
extern "C" void kernel_launch(void* const* d_in, const int* in_sizes, int n_in,
                              void* d_out, int out_size) {
    const float* imgs = (const float*)d_in[0];
    const float* caps = (const float*)d_in[1];
    const int* img_lens = (const int*)d_in[2];
    const int* cap_lens = (const int*)d_in[3];
    float* out = (float*)d_out;

    cudaFuncSetAttribute(norm_kernel,
                         cudaFuncAttributeMaxDynamicSharedMemorySize, NORM_SMEM_BYTES);
    cudaFuncSetAttribute(wass_kernel,
                         cudaFuncAttributeMaxDynamicSharedMemorySize, SMEM_BYTES);

    norm_kernel<<<BI + BT, 256, NORM_SMEM_BYTES>>>(imgs, caps);

    dim3 grid(BT / JP, BI / IP);  // (32, 64)
    wass_kernel<<<grid, 256, SMEM_BYTES>>>(img_lens, cap_lens, out);
}

// round 13
// speedup vs baseline: 1.0024x; 1.0024x over previous
#include <cuda_runtime.h>
#include <cuda_fp16.h>
#include <cstdint>

#define BI 128
#define BT 128
#define RR 36
#define WW 50
#define DD 256
#define ILAMB 20.0f     // 1/0.05
#define EPSV 1e-6f

#define IP 1            // imgs per block
#define JP 4            // caps per block
#define NPAIR 4         // pairs per CTA, 2 warps each
#define KC 32           // K-chunk (2 x k16 mma steps)
#define NCHUNK (DD / KC)   // 8
#define MT 3            // 48 rows padded
#define NT 7            // 56 cols padded
#define NKS (KC / 16)   // 2 k-steps per chunk
#define NKS_TOT (DD / 16)  // 16 global k-steps

// Pre-baked fp16 fragment layouts in gmem (u32 = f16x2), ks-major:
// A quad (4xu32/lane) at ((ksg*3+mt)*32 + lane): {a0,a1,a2,a3} of m16n8k16
// B pair (2xu32/lane) at ((ksg*7+nt)*32 + lane): {b0,b1}
#define A_IMG_U32 (NKS_TOT * MT * 128)   // 6144 per image
#define B_CAP_U32 (NKS_TOT * NT * 64)    // 7168 per cap
#define A_CHUNK_U32 (NKS * MT * 128)     // 768 per image per chunk
#define B_CHUNK_U32 (NKS * NT * 64)      // 896 per cap per chunk
#define A_REG_U32 (IP * A_CHUNK_U32)     // 768
#define B_REG_U32 (JP * B_CHUNK_U32)     // 3584
#define BUF_U32 (A_REG_U32 + B_REG_U32)  // 4352
#define BUF_BYTES (BUF_U32 * 4)          // 17408
#define NBUF 4

// Sinkhorn scratch (fp32; reuses the staging buffers after GEMM)
#define KW 58                           // even: float2 row dots
#define KS_STRIDE (RR * KW)             // 2088
#define AL_OFF (NPAIR * KS_STRIDE)      // 8352
#define BE_OFF (AL_OFF + NPAIR * RR)    // 8496
#define BET_STRIDE 52                   // WW + pad (float2 tail reads zeros)
#define RS_OFF (BE_OFF + NPAIR * BET_STRIDE)  // 8704 (+8 reduce slots)

#define SMEM_U32 (NBUF * BUF_U32)       // 17408 (> 8712 Sinkhorn floats)
#define SMEM_BYTES (SMEM_U32 * 4)       // 69632 ; x3 CTAs = 204 KB/SM

#define NORM_SMEM_BYTES (B_CAP_U32 * 4) // 28672 (max of A/B block)

__device__ uint32_t g_aq[BI * A_IMG_U32];
__device__ uint32_t g_bq[BT * B_CAP_U32];

__device__ __forceinline__ uint32_t pack_h2(float lo, float hi) {
    uint32_t r;
    asm("cvt.rn.f16x2.f32 %0, %1, %2;" : "=r"(r) : "f"(hi), "f"(lo));
    return r;
}

__device__ __forceinline__ void cp16(uint32_t dst, const void* src) {
    asm volatile("cp.async.cg.shared.global [%0], [%1], 16;\n"
                 :: "r"(dst), "l"(src));
}

#define PAIR_BAR(p) asm volatile("bar.sync %0, %1;" :: "r"(1 + (p)), "r"(64) : "memory")

// ---------------------------------------------------------------------------
// Kernel 1: L2-normalize, convert to fp16 pairs, build fragment layout in
// smem, dump coalesced. One block per image (b < BI) or cap (b >= BI).
// Lane L owns k-octet 8L..8L+7: ksg = L>>1, sel = L&1 (k-offset 8*sel).
// ---------------------------------------------------------------------------
__global__ __launch_bounds__(256)
void norm_kernel(const float* __restrict__ imgs,
                 const float* __restrict__ caps) {
    extern __shared__ uint32_t sm[];
    const int b = blockIdx.x;
    const int tid = threadIdx.x;
    const int lane = tid & 31;
    const int wrp = tid >> 5;
    const int ksg = lane >> 1;
    const int sel = lane & 1;

    if (b < BI) {
        for (int r = wrp; r < 48; r += 8) {
            float v[8];
            if (r < RR) {
                const float4* s4 = reinterpret_cast<const float4*>(
                    imgs + ((size_t)b * RR + r) * DD);
                float4 v0 = s4[2 * lane], v1 = s4[2 * lane + 1];
                float ss = v0.x * v0.x + v0.y * v0.y + v0.z * v0.z + v0.w * v0.w
                         + v1.x * v1.x + v1.y * v1.y + v1.z * v1.z + v1.w * v1.w;
#pragma unroll
                for (int o = 16; o > 0; o >>= 1)
                    ss += __shfl_xor_sync(0xffffffffu, ss, o);
                float inv = 1.0f / fmaxf(sqrtf(ss), 1e-8f);
                v[0] = v0.x * inv; v[1] = v0.y * inv;
                v[2] = v0.z * inv; v[3] = v0.w * inv;
                v[4] = v1.x * inv; v[5] = v1.y * inv;
                v[6] = v1.z * inv; v[7] = v1.w * inv;
            } else {
#pragma unroll
                for (int y = 0; y < 8; ++y) v[y] = 0.0f;
            }
            int mt = r >> 4, x = r & 15, g = x & 7, hi = x >> 3;
#pragma unroll
            for (int t = 0; t < 4; ++t) {
                sm[((ksg * 3 + mt) * 32 + g * 4 + t) * 4 + sel * 2 + hi] =
                    pack_h2(v[2 * t], v[2 * t + 1]);
            }
        }
        __syncthreads();
        uint4* dst = reinterpret_cast<uint4*>(g_aq + (size_t)b * A_IMG_U32);
        const uint4* src = reinterpret_cast<const uint4*>(sm);
#pragma unroll
        for (int s = 0; s < A_IMG_U32 / 4 / 256; ++s)
            dst[tid + s * 256] = src[tid + s * 256];
    } else {
        const int j = b - BI;
        for (int w = wrp; w < 56; w += 8) {
            float v[8];
            if (w < WW) {
                const float4* s4 = reinterpret_cast<const float4*>(
                    caps + ((size_t)j * WW + w) * DD);
                float4 v0 = s4[2 * lane], v1 = s4[2 * lane + 1];
                float ss = v0.x * v0.x + v0.y * v0.y + v0.z * v0.z + v0.w * v0.w
                         + v1.x * v1.x + v1.y * v1.y + v1.z * v1.z + v1.w * v1.w;
#pragma unroll
                for (int o = 16; o > 0; o >>= 1)
                    ss += __shfl_xor_sync(0xffffffffu, ss, o);
                float inv = 1.0f / fmaxf(sqrtf(ss), 1e-8f);
                v[0] = v0.x * inv; v[1] = v0.y * inv;
                v[2] = v0.z * inv; v[3] = v0.w * inv;
                v[4] = v1.x * inv; v[5] = v1.y * inv;
                v[6] = v1.z * inv; v[7] = v1.w * inv;
            } else {
#pragma unroll
                for (int y = 0; y < 8; ++y) v[y] = 0.0f;
            }
            int nt = w >> 3, g = w & 7;
#pragma unroll
            for (int t = 0; t < 4; ++t) {
                sm[((ksg * 7 + nt) * 32 + g * 4 + t) * 2 + sel] =
                    pack_h2(v[2 * t], v[2 * t + 1]);
            }
        }
        __syncthreads();
        uint4* dst = reinterpret_cast<uint4*>(g_bq + (size_t)j * B_CAP_U32);
        const uint4* src = reinterpret_cast<const uint4*>(sm);
#pragma unroll
        for (int s = 0; s < B_CAP_U32 / 4 / 256; ++s)
            dst[tid + s * 256] = src[tid + s * 256];
    }
}

// ---------------------------------------------------------------------------
// m16n8k16 fp16 mma, fp32 accumulate
// ---------------------------------------------------------------------------
__device__ __forceinline__ void mma_f16(float* c, const uint4& a, const uint2& b) {
    asm volatile(
        "mma.sync.aligned.m16n8k16.row.col.f32.f16.f16.f32 "
        "{%0,%1,%2,%3}, {%4,%5,%6,%7}, {%8,%9}, {%0,%1,%2,%3};\n"
        : "+f"(c[0]), "+f"(c[1]), "+f"(c[2]), "+f"(c[3])
        : "r"(a.x), "r"(a.y), "r"(a.z), "r"(a.w), "r"(b.x), "r"(b.y));
}

// ---------------------------------------------------------------------------
// Kernel 2: fused GEMM + Sinkhorn. 256 threads = 1 img x 4 caps = 4 pairs,
// 2 warps per pair (warp w: pair p = w>>1, half h = w&1, N-tiles h*4..).
// 3 CTAs/SM via __launch_bounds__(256,3) -> 24 warps/SM.
// ---------------------------------------------------------------------------
__global__ __launch_bounds__(256, 3)
void wass_kernel(const int* __restrict__ img_lens,
                 const int* __restrict__ cap_lens,
                 float* __restrict__ out) {
    extern __shared__ float smem[];
    uint32_t* sm32 = reinterpret_cast<uint32_t*>(smem);
    const int i = blockIdx.y;            // IP = 1
    const int j0 = blockIdx.x * JP;
    const int tid = threadIdx.x;
    const int lane = tid & 31;
    const int wid = tid >> 5;
    const int gid = lane >> 2;
    const int tig = lane & 3;
    const int p = wid >> 1;
    const int h = wid & 1;
    const int nbase = h * 4;
    const int ntw = 4 - h;               // 4 or 3 N-tiles

    uint32_t sb;
    asm("{ .reg .u64 t; cvta.to.shared.u64 t, %1; cvt.u32.u64 %0, t; }"
        : "=r"(sb) : "l"(smem));

    // --- per-thread staging assignment (constant; src advances per chunk) ---
    // A: 192 quads/chunk (tid < 192, one each).
    // B: 64 threads per cap; quads tB+64s, s=0..3 (s=3 only if tB<32; 224/cap).
    const bool aOn = (tid < 192);
    const uint32_t* srcA = g_aq + (size_t)i * A_IMG_U32 + tid * 4;
    const uint32_t dstA = (uint32_t)(tid * 16);
    const int capB = tid >> 6, tB = tid & 63;
    const uint32_t* srcB = g_bq + (size_t)(j0 + capB) * B_CAP_U32 + tB * 4;
    const uint32_t dstB = (uint32_t)(3072 + capB * 3584 + tB * 16);
    const bool b4 = (tB < 32);

    float C[MT][4][4];
#pragma unroll
    for (int mt = 0; mt < MT; ++mt)
#pragma unroll
        for (int nt = 0; nt < 4; ++nt)
#pragma unroll
            for (int c = 0; c < 4; ++c) C[mt][nt][c] = 0.0f;

    auto do_stage = [&](int s) {
        uint32_t bufb = sb + (uint32_t)(s & (NBUF - 1)) * BUF_BYTES;
        if (aOn) cp16(bufb + dstA, srcA);
        cp16(bufb + dstB, srcB);
        cp16(bufb + dstB + 1024, srcB + 256);
        cp16(bufb + dstB + 2048, srcB + 512);
        if (b4) cp16(bufb + dstB + 3072, srcB + 768);
        srcA += A_CHUNK_U32;
        srcB += B_CHUNK_U32;
        asm volatile("cp.async.commit_group;" ::: "memory");
    };

    // prologue: chunks 0 and 1 in flight
    do_stage(0);
    do_stage(1);

    for (int ch = 0; ch < NCHUNK; ++ch) {
        if (ch < NCHUNK - 1) {
            asm volatile("cp.async.wait_group 1;" ::: "memory");
        } else {
            asm volatile("cp.async.wait_group 0;" ::: "memory");
        }
        __syncthreads();
        if (ch + 2 < NCHUNK) do_stage(ch + 2);

        const uint32_t* buf = sm32 + (ch & (NBUF - 1)) * BUF_U32;
        const uint4* Aq = reinterpret_cast<const uint4*>(buf);
        const uint2* Bq = reinterpret_cast<const uint2*>(buf + A_REG_U32)
                        + p * (B_CHUNK_U32 / 2);
#pragma unroll
        for (int ks = 0; ks < NKS; ++ks) {
            uint4 a[MT];
#pragma unroll
            for (int mt = 0; mt < MT; ++mt)
                a[mt] = Aq[(ks * 3 + mt) * 32 + lane];       // one LDS.128
#pragma unroll
            for (int nt = 0; nt < 4; ++nt) {
                if (nt < ntw) {
                    uint2 b = Bq[(ks * 7 + nbase + nt) * 32 + lane]; // LDS.64
#pragma unroll
                    for (int mt = 0; mt < MT; ++mt) mma_f16(C[mt][nt], a[mt], b);
                }
            }
        }
    }
    __syncthreads();   // all compute done; staging region reused for Sinkhorn

    // ---------------- Sinkhorn (2 warps = 64 threads per pair) ----------------
    const int j = j0 + p;
    const int Ri = img_lens[i];
    const int Wj = cap_lens[j];
    float* Kp  = smem + p * KS_STRIDE;              // [36][58]
    float* alp = smem + AL_OFF + p * RR;            // [36]
    float* bet = smem + BE_OFF + p * BET_STRIDE;    // [52]
    float* red = smem + RS_OFF;                     // [8]
    const int t64 = h * 32 + lane;

    // K = exp((s-1)/lambda) masked; partial total sum per warp.
    float tsum = 0.0f;
#pragma unroll
    for (int mt = 0; mt < MT; ++mt) {
        if (mt * 16 < Ri) {
#pragma unroll
            for (int nt = 0; nt < 4; ++nt) {
                if (nt < ntw && (nbase + nt) * 8 < Wj) {
#pragma unroll
                    for (int c = 0; c < 4; ++c) {
                        int r = mt * 16 + gid + ((c >> 1) << 3);
                        int w = (nbase + nt) * 8 + (tig << 1) + (c & 1);
                        if (r < Ri && w < Wj) {
                            float s = C[mt][nt][c];
                            float k = __expf(ILAMB * s - ILAMB);
                            Kp[r * KW + w] = k;
                            tsum += k;
                        }
                    }
                }
            }
        }
    }
#pragma unroll
    for (int o = 16; o > 0; o >>= 1) tsum += __shfl_xor_sync(0xffffffffu, tsum, o);
    if (lane == 0) red[wid] = tsum;
    // bet with zeroed pad element (odd Wj) so float2 row-dot tails read zeros
    if (t64 < Wj + (Wj & 1)) bet[t64] = (t64 < Wj) ? 1.0f : 0.0f;
    if ((Wj & 1) && t64 < Ri) Kp[t64 * KW + Wj] = 0.0f;
    PAIR_BAR(p);

    float alpha0 = 1.0f / (red[2 * p] + red[2 * p + 1] + EPSV);
    if (t64 < Ri) alp[t64] = alpha0;
    const float rm = 1.0f / (float)Ri;
    const float cm = 1.0f / (float)Wj;
    PAIR_BAR(p);

    const int nh = (Wj + 1) >> 1;
#pragma unroll
    for (int it = 0; it < 3; ++it) {
        if (t64 < Ri) {
            const float2* kr = reinterpret_cast<const float2*>(Kp + t64 * KW);
            const float2* b2 = reinterpret_cast<const float2*>(bet);
            float dot = 0.0f;
            for (int t = 0; t < nh; ++t) {
                float2 kv = kr[t], bv = b2[t];
                dot += kv.x * bv.x;
                dot += kv.y * bv.y;
            }
            float a = alp[t64];
            alp[t64] = a * (rm / (a * dot + EPSV));
        }
        PAIR_BAR(p);
        if (t64 < Wj) {
            float dot = 0.0f;
            for (int r = 0; r < Ri; ++r) dot += Kp[r * KW + t64] * alp[r];
            float b = bet[t64];
            bet[t64] = b * (cm / (b * dot + EPSV));
        }
        PAIR_BAR(p);
    }

    // final: sum s * K * alpha_r * beta_w; K re-read from smem (bit-identical)
    float acc = 0.0f;
#pragma unroll
    for (int mt = 0; mt < MT; ++mt) {
        if (mt * 16 < Ri) {
#pragma unroll
            for (int nt = 0; nt < 4; ++nt) {
                if (nt < ntw && (nbase + nt) * 8 < Wj) {
#pragma unroll
                    for (int c = 0; c < 4; ++c) {
                        int r = mt * 16 + gid + ((c >> 1) << 3);
                        int w = (nbase + nt) * 8 + (tig << 1) + (c & 1);
                        if (r < Ri && w < Wj) {
                            float s = C[mt][nt][c];
                            float k = Kp[r * KW + w];
                            acc += s * k * alp[r] * bet[w];
                        }
                    }
                }
            }
        }
    }
#pragma unroll
    for (int o = 16; o > 0; o >>= 1) acc += __shfl_xor_sync(0xffffffffu, acc, o);
    if (lane == 0) red[wid] = acc;
    PAIR_BAR(p);
    if (h == 0 && lane == 0)
        out[i * BT + j] = red[2 * p] + red[2 * p + 1];
}

// ---------------------------------------------------------------------------
extern "C" void kernel_launch(void* const* d_in, const int* in_sizes, int n_in,
                              void* d_out, int out_size) {
    const float* imgs = (const float*)d_in[0];
    const float* caps = (const float*)d_in[1];
    const int* img_lens = (const int*)d_in[2];
    const int* cap_lens = (const int*)d_in[3];
    float* out = (float*)d_out;

    cudaFuncSetAttribute(norm_kernel,
                         cudaFuncAttributeMaxDynamicSharedMemorySize, NORM_SMEM_BYTES);
    cudaFuncSetAttribute(wass_kernel,
                         cudaFuncAttributeMaxDynamicSharedMemorySize, SMEM_BYTES);

    norm_kernel<<<BI + BT, 256, NORM_SMEM_BYTES>>>(imgs, caps);

    dim3 grid(BT / JP, BI);  // (32, 128)
    wass_kernel<<<grid, 256, SMEM_BYTES>>>(img_lens, cap_lens, out);
}

// round 14
// speedup vs baseline: 1.1528x; 1.1500x over previous
#include <cuda_runtime.h>
#include <cuda_fp16.h>
#include <cstdint>

#define BI 128
#define BT 128
#define RR 36
#define WW 50
#define DD 256
#define EPSV 1e-6f

#define MROWS (BI * RR)      // 4608 = 36 * 128
#define NCOLS (BT * WW)      // 6400 = 50 * 128
#define MB 36                // M blocks of 128
#define NB 50                // N blocks of 128
#define NKSG 16              // k16 groups
#define NCHUNK 8             // chunks of 2 ksg
#define NBUF 4

// Fragment layouts in gmem (u32 = f16x2):
// g_aq[mb][ksg][mt(8)][lane(32)][q(4)]  -> 16384 u32 per mb
// g_bq[nb][ksg][nt(16)][lane(32)][p(2)] -> 16384 u32 per nb
#define ABLK_U32 16384
#define BBLK_U32 16384
#define CHUNK_U32 2048        // per chunk per tensor (2 ksg x 1024)
#define GBUF_U32 4096         // A chunk + B chunk
#define GBUF_BYTES 16384
#define GEMM_SMEM (NBUF * GBUF_BYTES)   // 65536

// sims: pair-blocked fp16 [pair(16384)][r(36)][w(50)]
#define PAIR_ELEMS 1800

// Sinkhorn smem (per 8-warp CTA)
#define KW 58
#define KS_STRIDE (RR * KW)             // 2088
#define AL_OFF (8 * KS_STRIDE)          // 16704
#define BE_OFF (AL_OFF + 8 * RR)        // 16992
#define BET_STRIDE 52
#define SINK_SMEM ((BE_OFF + 8 * BET_STRIDE) * 4)   // 69632

#define NORM_SMEM (ABLK_U32 * 4)        // 65536

__device__ uint32_t g_aq[MB * ABLK_U32];
__device__ uint32_t g_bq[NB * BBLK_U32];
__device__ uint16_t g_sims[(size_t)BI * BT * PAIR_ELEMS];   // 59 MB fp16

__device__ __forceinline__ uint32_t pack_h2(float lo, float hi) {
    uint32_t r;
    asm("cvt.rn.f16x2.f32 %0, %1, %2;" : "=r"(r) : "f"(hi), "f"(lo));
    return r;
}

__device__ __forceinline__ void cp16(uint32_t dst, const void* src) {
    asm volatile("cp.async.cg.shared.global [%0], [%1], 16;\n"
                 :: "r"(dst), "l"(src));
}

// ---------------------------------------------------------------------------
// Kernel 1: L2-normalize + fp16 convert + fragment prebake.
// Block b < MB: A block (128 global img-rows). Else B block (128 cap-rows).
// Warp per row; lane L owns k-octet: ksg = L>>1, sel = L&1.
// ---------------------------------------------------------------------------
__global__ __launch_bounds__(256)
void norm_kernel(const float* __restrict__ imgs,
                 const float* __restrict__ caps) {
    extern __shared__ uint32_t sm[];
    const int b = blockIdx.x;
    const int tid = threadIdx.x;
    const int lane = tid & 31;
    const int wrp = tid >> 5;
    const int ksg = lane >> 1;
    const int sel = lane & 1;

    const bool isA = (b < MB);
    const float* src_base = isA ? imgs : caps;
    const int blk = isA ? b : b - MB;

    for (int rr = wrp; rr < 128; rr += 8) {
        const int gr = blk * 128 + rr;       // global row/col index
        const float4* s4 = reinterpret_cast<const float4*>(
            src_base + (size_t)gr * DD);
        float4 v0 = s4[2 * lane], v1 = s4[2 * lane + 1];
        float ss = v0.x * v0.x + v0.y * v0.y + v0.z * v0.z + v0.w * v0.w
                 + v1.x * v1.x + v1.y * v1.y + v1.z * v1.z + v1.w * v1.w;
#pragma unroll
        for (int o = 16; o > 0; o >>= 1)
            ss += __shfl_xor_sync(0xffffffffu, ss, o);
        float inv = 1.0f / fmaxf(sqrtf(ss), 1e-8f);
        float v[8];
        v[0] = v0.x * inv; v[1] = v0.y * inv;
        v[2] = v0.z * inv; v[3] = v0.w * inv;
        v[4] = v1.x * inv; v[5] = v1.y * inv;
        v[6] = v1.z * inv; v[7] = v1.w * inv;

        if (isA) {
            int mt = rr >> 4, x = rr & 15, g = x & 7, hi = x >> 3;
#pragma unroll
            for (int t = 0; t < 4; ++t)
                sm[((ksg * 8 + mt) * 32 + g * 4 + t) * 4 + sel * 2 + hi] =
                    pack_h2(v[2 * t], v[2 * t + 1]);
        } else {
            int nt = rr >> 3, g = rr & 7;
#pragma unroll
            for (int t = 0; t < 4; ++t)
                sm[((ksg * 16 + nt) * 32 + g * 4 + t) * 2 + sel] =
                    pack_h2(v[2 * t], v[2 * t + 1]);
        }
    }
    __syncthreads();
    uint4* dst = reinterpret_cast<uint4*>(
        (isA ? g_aq + (size_t)blk * ABLK_U32 : g_bq + (size_t)blk * BBLK_U32));
    const uint4* s4 = reinterpret_cast<const uint4*>(sm);
#pragma unroll
    for (int s = 0; s < ABLK_U32 / 4 / 256; ++s)
        dst[tid + s * 256] = s4[tid + s * 256];
}

// ---------------------------------------------------------------------------
// m16n8k16 fp16 mma, fp32 accumulate
// ---------------------------------------------------------------------------
__device__ __forceinline__ void mma_f16(float* c, const uint4& a, const uint2& b) {
    asm volatile(
        "mma.sync.aligned.m16n8k16.row.col.f32.f16.f16.f32 "
        "{%0,%1,%2,%3}, {%4,%5,%6,%7}, {%8,%9}, {%0,%1,%2,%3};\n"
        : "+f"(c[0]), "+f"(c[1]), "+f"(c[2]), "+f"(c[3])
        : "r"(a.x), "r"(a.y), "r"(a.z), "r"(a.w), "r"(b.x), "r"(b.y));
}

// ---------------------------------------------------------------------------
// Kernel 2: pure GEMM 4608x6400x256 fp16->fp16 sims (pair-blocked output).
// CTA = 128x128 tile; 8 warps 2x4, each 64x32 (4 m-tiles x 4 n-tiles).
// ---------------------------------------------------------------------------
__global__ __launch_bounds__(256, 2)
void gemm_kernel() {
    extern __shared__ uint32_t sm32[];
    const int nb = blockIdx.x;
    const int mb = blockIdx.y;
    const int tid = threadIdx.x;
    const int lane = tid & 31;
    const int wid = tid >> 5;
    const int gid = lane >> 2;
    const int tig = lane & 3;
    const int wr = wid >> 2;      // 0..1
    const int wc = wid & 3;       // 0..3

    uint32_t sb;
    asm("{ .reg .u64 t; cvta.to.shared.u64 t, %1; cvt.u32.u64 %0, t; }"
        : "=r"(sb) : "l"(sm32));

    const uint32_t* srcA = g_aq + (size_t)mb * ABLK_U32 + tid * 4;
    const uint32_t* srcB = g_bq + (size_t)nb * BBLK_U32 + tid * 4;
    const uint32_t dA = (uint32_t)(tid * 16);
    const uint32_t dB = (uint32_t)(8192 + tid * 16);

    float C[4][4][4];
#pragma unroll
    for (int mt = 0; mt < 4; ++mt)
#pragma unroll
        for (int nt = 0; nt < 4; ++nt)
#pragma unroll
            for (int c = 0; c < 4; ++c) C[mt][nt][c] = 0.0f;

    auto do_stage = [&](int s) {
        uint32_t bufb = sb + (uint32_t)(s & (NBUF - 1)) * GBUF_BYTES;
        cp16(bufb + dA, srcA);
        cp16(bufb + dA + 4096, srcA + 1024);
        cp16(bufb + dB, srcB);
        cp16(bufb + dB + 4096, srcB + 1024);
        srcA += CHUNK_U32;
        srcB += CHUNK_U32;
        asm volatile("cp.async.commit_group;" ::: "memory");
    };

    do_stage(0);
    do_stage(1);

    for (int ch = 0; ch < NCHUNK; ++ch) {
        if (ch < NCHUNK - 1) {
            asm volatile("cp.async.wait_group 1;" ::: "memory");
        } else {
            asm volatile("cp.async.wait_group 0;" ::: "memory");
        }
        __syncthreads();
        if (ch + 2 < NCHUNK) do_stage(ch + 2);

        const uint32_t* buf = sm32 + (ch & (NBUF - 1)) * GBUF_U32;
        const uint4* Aq = reinterpret_cast<const uint4*>(buf);
        const uint2* Bq = reinterpret_cast<const uint2*>(buf + 2048);
#pragma unroll
        for (int ks = 0; ks < 2; ++ks) {
            uint4 a[4];
#pragma unroll
            for (int mt = 0; mt < 4; ++mt)
                a[mt] = Aq[(ks * 8 + wr * 4 + mt) * 32 + lane];
#pragma unroll
            for (int nt = 0; nt < 4; ++nt) {
                uint2 b = Bq[(ks * 16 + wc * 4 + nt) * 32 + lane];
#pragma unroll
                for (int mt = 0; mt < 4; ++mt) mma_f16(C[mt][nt], a[mt], b);
            }
        }
        __syncthreads();
    }

    // Epilogue: write fp16 sims pair-blocked [i*128+j][r][w].
    unsigned jj[4], ww[4];
#pragma unroll
    for (int nt = 0; nt < 4; ++nt) {
        unsigned Cc = nb * 128 + (wc * 4 + nt) * 8 + 2 * tig;  // even
        jj[nt] = Cc / 50u;
        ww[nt] = Cc - jj[nt] * 50u;                            // even
    }
#pragma unroll
    for (int mt = 0; mt < 4; ++mt) {
#pragma unroll
        for (int hh = 0; hh < 2; ++hh) {
            unsigned R = mb * 128 + (wr * 4 + mt) * 16 + gid + 8 * hh;
            unsigned ii = R / 36u;
            unsigned r = R - ii * 36u;
            unsigned rowbase = (ii << 7) * PAIR_ELEMS + r * 50u;
#pragma unroll
            for (int nt = 0; nt < 4; ++nt) {
                uint32_t pk = pack_h2(C[mt][nt][2 * hh], C[mt][nt][2 * hh + 1]);
                size_t idx = rowbase + jj[nt] * PAIR_ELEMS + ww[nt];
                *reinterpret_cast<uint32_t*>(g_sims + idx) = pk;
            }
        }
    }
}

// ---------------------------------------------------------------------------
// Kernel 3: Sinkhorn. Warp-private pair; 8 pairs per 256-thr CTA.
// Loops bounded by runtime Ri/Wj. Masked K entries stored as exact 0.
// ---------------------------------------------------------------------------
__global__ __launch_bounds__(256, 3)
void sinkhorn_kernel(const int* __restrict__ img_lens,
                     const int* __restrict__ cap_lens,
                     float* __restrict__ out) {
    extern __shared__ float smem[];
    const int tid = threadIdx.x;
    const int lane = tid & 31;
    const int wid = tid >> 5;
    const int pid = blockIdx.x * 8 + wid;
    const int i = pid >> 7;
    const int j = pid & 127;
    const int Ri = img_lens[i];
    const int Wj = cap_lens[j];

    const uint32_t* S32 = reinterpret_cast<const uint32_t*>(
        g_sims + (size_t)pid * PAIR_ELEMS);          // row stride 25 u32
    float* Kp = smem + wid * KS_STRIDE;              // [36][58]
    float* alp = smem + AL_OFF + wid * RR;
    float* bet = smem + BE_OFF + wid * BET_STRIDE;

    const int nh = (Wj + 1) >> 1;

    // load + exp + K store (masked entries -> 0); total sum
    float tsum = 0.0f;
    for (int r = lane; r < Ri; r += 32) {
        const uint32_t* row = S32 + r * 25;
        float* kr = Kp + r * KW;
        for (int t = 0; t < nh; ++t) {
            __half2 hv = *reinterpret_cast<const __half2*>(&row[t]);
            float2 f = __half22float2(hv);
            float k0 = __expf(20.0f * f.x - 20.0f);
            float k1 = (2 * t + 1 < Wj) ? __expf(20.0f * f.y - 20.0f) : 0.0f;
            *reinterpret_cast<float2*>(kr + 2 * t) = make_float2(k0, k1);
            tsum += k0 + k1;
        }
    }
#pragma unroll
    for (int o = 16; o > 0; o >>= 1) tsum += __shfl_xor_sync(0xffffffffu, tsum, o);
    float alpha0 = 1.0f / (tsum + EPSV);

    for (int r = lane; r < Ri; r += 32) alp[r] = alpha0;
    for (int w = lane; w < Wj + (Wj & 1); w += 32)
        bet[w] = (w < Wj) ? 1.0f : 0.0f;
    const float rm = 1.0f / (float)Ri;
    const float cm = 1.0f / (float)Wj;
    __syncwarp();

#pragma unroll
    for (int it = 0; it < 3; ++it) {
        for (int r = lane; r < Ri; r += 32) {
            const float2* kr = reinterpret_cast<const float2*>(Kp + r * KW);
            const float2* b2 = reinterpret_cast<const float2*>(bet);
            float dot = 0.0f;
            for (int t = 0; t < nh; ++t) {
                float2 kv = kr[t], bv = b2[t];
                dot += kv.x * bv.x;
                dot += kv.y * bv.y;
            }
            float a = alp[r];
            alp[r] = a * (rm / (a * dot + EPSV));
        }
        __syncwarp();
        for (int w = lane; w < Wj; w += 32) {
            float dot = 0.0f;
            for (int r = 0; r < Ri; ++r) dot += Kp[r * KW + w] * alp[r];
            float b = bet[w];
            bet[w] = b * (cm / (b * dot + EPSV));
        }
        __syncwarp();
    }

    // final: sum s * K * alp * bet  (K==0 where masked, so no guards needed)
    float acc = 0.0f;
    for (int r = lane; r < Ri; r += 32) {
        const uint32_t* row = S32 + r * 25;
        const float2* kr = reinterpret_cast<const float2*>(Kp + r * KW);
        const float2* b2 = reinterpret_cast<const float2*>(bet);
        float racc = 0.0f;
        for (int t = 0; t < nh; ++t) {
            __half2 hv = *reinterpret_cast<const __half2*>(&row[t]);
            float2 f = __half22float2(hv);
            float2 kv = kr[t], bv = b2[t];
            racc += f.x * kv.x * bv.x;
            racc += f.y * kv.y * bv.y;
        }
        acc += alp[r] * racc;
    }
#pragma unroll
    for (int o = 16; o > 0; o >>= 1) acc += __shfl_xor_sync(0xffffffffu, acc, o);
    if (lane == 0) out[i * BT + j] = acc;
}

// ---------------------------------------------------------------------------
extern "C" void kernel_launch(void* const* d_in, const int* in_sizes, int n_in,
                              void* d_out, int out_size) {
    const float* imgs = (const float*)d_in[0];
    const float* caps = (const float*)d_in[1];
    const int* img_lens = (const int*)d_in[2];
    const int* cap_lens = (const int*)d_in[3];
    float* out = (float*)d_out;

    cudaFuncSetAttribute(norm_kernel,
                         cudaFuncAttributeMaxDynamicSharedMemorySize, NORM_SMEM);
    cudaFuncSetAttribute(gemm_kernel,
                         cudaFuncAttributeMaxDynamicSharedMemorySize, GEMM_SMEM);
    cudaFuncSetAttribute(sinkhorn_kernel,
                         cudaFuncAttributeMaxDynamicSharedMemorySize, SINK_SMEM);

    norm_kernel<<<MB + NB, 256, NORM_SMEM>>>(imgs, caps);
    gemm_kernel<<<dim3(NB, MB), 256, GEMM_SMEM>>>();
    sinkhorn_kernel<<<(BI * BT) / 8, 256, SINK_SMEM>>>(img_lens, cap_lens, out);
}

// round 15
// speedup vs baseline: 1.2144x; 1.0534x over previous
#include <cuda_runtime.h>
#include <cuda_fp16.h>
#include <cstdint>

#define BI 128
#define BT 128
#define RR 36
#define WW 50
#define DD 256
#define EPSV 1e-6f

#define MB 36                // M blocks of 128 (4608 rows)
#define NB 50                // N blocks of 128 (6400 cols)
#define NCHUNK 8             // chunks of 2 ksg
#define NBUF 4

// Fragment layouts in gmem (u32 = f16x2):
// g_aq[mb][ksg][mt(8)][lane(32)][q(4)]  -> 16384 u32 per mb
// g_bq[nb][ksg][nt(16)][lane(32)][p(2)] -> 16384 u32 per nb
#define ABLK_U32 16384
#define BBLK_U32 16384
#define CHUNK_U32 2048        // per chunk per tensor (2 ksg x 1024)
#define GBUF_U32 4096         // A chunk + B chunk
#define GBUF_BYTES 16384
#define GEMM_SMEM (NBUF * GBUF_BYTES)   // 65536

// sims: pair-blocked fp16 [pair(16384)][r(36)][w(50)]
#define PAIR_ELEMS 1800

// Sinkhorn smem (per 8-warp CTA)
#define KW 58
#define KS_STRIDE (RR * KW)             // 2088
#define AL_OFF (8 * KS_STRIDE)          // 16704
#define BE_OFF (AL_OFF + 8 * RR)        // 16992
#define BET_STRIDE 52
#define SINK_SMEM ((BE_OFF + 8 * BET_STRIDE) * 4)   // 69632

#define NORM_SMEM 16384      // one quarter-block staged

__device__ uint32_t g_aq[MB * ABLK_U32];
__device__ uint32_t g_bq[NB * BBLK_U32];
__device__ uint16_t g_sims[(size_t)BI * BT * PAIR_ELEMS];   // 59 MB fp16

__device__ __forceinline__ uint32_t pack_h2(float lo, float hi) {
    uint32_t r;
    asm("cvt.rn.f16x2.f32 %0, %1, %2;" : "=r"(r) : "f"(hi), "f"(lo));
    return r;
}

__device__ __forceinline__ void cp16(uint32_t dst, const void* src) {
    asm volatile("cp.async.cg.shared.global [%0], [%1], 16;\n"
                 :: "r"(dst), "l"(src));
}

// ---------------------------------------------------------------------------
// Kernel 1: L2-normalize + fp16 + fragment prebake, 4 CTAs per 128-row block.
// CTA (b, q): rows q*32 .. q*32+31 of block b. A quarter owns mt {2q,2q+1};
// B quarter owns nt {4q..4q+3}. Staged compact in 16 KB smem, dumped as
// 16 contiguous 1 KB chunks (one per ksg).
// ---------------------------------------------------------------------------
__global__ __launch_bounds__(256)
void norm_kernel(const float* __restrict__ imgs,
                 const float* __restrict__ caps) {
    extern __shared__ uint32_t sm[];
    const int bq = blockIdx.x;
    const int b = bq >> 2;
    const int q = bq & 3;
    const int tid = threadIdx.x;
    const int lane = tid & 31;
    const int wrp = tid >> 5;
    const int ksg = lane >> 1;
    const int sel = lane & 1;

    const bool isA = (b < MB);
    const float* src_base = isA ? imgs : caps;
    const int blk = isA ? b : b - MB;

#pragma unroll
    for (int it = 0; it < 4; ++it) {
        const int rr = q * 32 + wrp + 8 * it;
        const int gr = blk * 128 + rr;
        const float4* s4 = reinterpret_cast<const float4*>(
            src_base + (size_t)gr * DD);
        float4 v0 = s4[2 * lane], v1 = s4[2 * lane + 1];
        float ss = v0.x * v0.x + v0.y * v0.y + v0.z * v0.z + v0.w * v0.w
                 + v1.x * v1.x + v1.y * v1.y + v1.z * v1.z + v1.w * v1.w;
#pragma unroll
        for (int o = 16; o > 0; o >>= 1)
            ss += __shfl_xor_sync(0xffffffffu, ss, o);
        float inv = 1.0f / fmaxf(sqrtf(ss), 1e-8f);
        float v[8];
        v[0] = v0.x * inv; v[1] = v0.y * inv;
        v[2] = v0.z * inv; v[3] = v0.w * inv;
        v[4] = v1.x * inv; v[5] = v1.y * inv;
        v[6] = v1.z * inv; v[7] = v1.w * inv;

        if (isA) {
            int mtl = ((rr >> 4) & 1);        // local mt within quarter (0..1)
            int x = rr & 15, g = x & 7, hi = x >> 3;
#pragma unroll
            for (int t = 0; t < 4; ++t)
                sm[((ksg * 2 + mtl) * 32 + g * 4 + t) * 4 + sel * 2 + hi] =
                    pack_h2(v[2 * t], v[2 * t + 1]);
        } else {
            int ntl = (rr >> 3) & 3;          // local nt within quarter (0..3)
            int g = rr & 7;
#pragma unroll
            for (int t = 0; t < 4; ++t)
                sm[((ksg * 4 + ntl) * 32 + g * 4 + t) * 2 + sel] =
                    pack_h2(v[2 * t], v[2 * t + 1]);
        }
    }
    __syncthreads();

    // Dump: 1024 uint4 total, 4 per thread. Chunk c = ksg (64 uint4 each).
    const uint4* s4 = reinterpret_cast<const uint4*>(sm);
    if (isA) {
        uint4* dst = reinterpret_cast<uint4*>(g_aq + (size_t)blk * ABLK_U32);
#pragma unroll
        for (int s = 0; s < 4; ++s) {
            int idx = tid + s * 256;
            int kk = idx >> 6, off = idx & 63;
            dst[(kk * 8 + 2 * q) * 32 + off] = s4[idx];
        }
    } else {
        uint4* dst = reinterpret_cast<uint4*>(g_bq + (size_t)blk * BBLK_U32);
#pragma unroll
        for (int s = 0; s < 4; ++s) {
            int idx = tid + s * 256;
            int kk = idx >> 6, off = idx & 63;
            dst[(kk * 16 + 4 * q) * 16 + off] = s4[idx];
        }
    }
}

// ---------------------------------------------------------------------------
// m16n8k16 fp16 mma, fp32 accumulate
// ---------------------------------------------------------------------------
__device__ __forceinline__ void mma_f16(float* c, const uint4& a, const uint2& b) {
    asm volatile(
        "mma.sync.aligned.m16n8k16.row.col.f32.f16.f16.f32 "
        "{%0,%1,%2,%3}, {%4,%5,%6,%7}, {%8,%9}, {%0,%1,%2,%3};\n"
        : "+f"(c[0]), "+f"(c[1]), "+f"(c[2]), "+f"(c[3])
        : "r"(a.x), "r"(a.y), "r"(a.z), "r"(a.w), "r"(b.x), "r"(b.y));
}

// ---------------------------------------------------------------------------
// Kernel 2: pure GEMM 4608x6400x256 fp16->fp16 sims (pair-blocked output).
// CTA = 128x128 tile; 8 warps 2x4, each 64x32. Single barrier per chunk.
// ---------------------------------------------------------------------------
__global__ __launch_bounds__(256, 2)
void gemm_kernel() {
    extern __shared__ uint32_t sm32[];
    const int nb = blockIdx.x;
    const int mb = blockIdx.y;
    const int tid = threadIdx.x;
    const int lane = tid & 31;
    const int wid = tid >> 5;
    const int gid = lane >> 2;
    const int tig = lane & 3;
    const int wr = wid >> 2;      // 0..1
    const int wc = wid & 3;       // 0..3

    uint32_t sb;
    asm("{ .reg .u64 t; cvta.to.shared.u64 t, %1; cvt.u32.u64 %0, t; }"
        : "=r"(sb) : "l"(sm32));

    const uint32_t* srcA = g_aq + (size_t)mb * ABLK_U32 + tid * 4;
    const uint32_t* srcB = g_bq + (size_t)nb * BBLK_U32 + tid * 4;
    const uint32_t dA = (uint32_t)(tid * 16);
    const uint32_t dB = (uint32_t)(8192 + tid * 16);

    float C[4][4][4];
#pragma unroll
    for (int mt = 0; mt < 4; ++mt)
#pragma unroll
        for (int nt = 0; nt < 4; ++nt)
#pragma unroll
            for (int c = 0; c < 4; ++c) C[mt][nt][c] = 0.0f;

    auto do_stage = [&](int s) {
        uint32_t bufb = sb + (uint32_t)(s & (NBUF - 1)) * GBUF_BYTES;
        cp16(bufb + dA, srcA);
        cp16(bufb + dA + 4096, srcA + 1024);
        cp16(bufb + dB, srcB);
        cp16(bufb + dB + 4096, srcB + 1024);
        srcA += CHUNK_U32;
        srcB += CHUNK_U32;
        asm volatile("cp.async.commit_group;" ::: "memory");
    };

    do_stage(0);
    do_stage(1);

    for (int ch = 0; ch < NCHUNK; ++ch) {
        if (ch < NCHUNK - 1) {
            asm volatile("cp.async.wait_group 1;" ::: "memory");
        } else {
            asm volatile("cp.async.wait_group 0;" ::: "memory");
        }
        __syncthreads();            // single barrier per chunk
        if (ch + 2 < NCHUNK) do_stage(ch + 2);

        const uint32_t* buf = sm32 + (ch & (NBUF - 1)) * GBUF_U32;
        const uint4* Aq = reinterpret_cast<const uint4*>(buf);
        const uint2* Bq = reinterpret_cast<const uint2*>(buf + 2048);
#pragma unroll
        for (int ks = 0; ks < 2; ++ks) {
            uint4 a[4];
#pragma unroll
            for (int mt = 0; mt < 4; ++mt)
                a[mt] = Aq[(ks * 8 + wr * 4 + mt) * 32 + lane];
#pragma unroll
            for (int nt = 0; nt < 4; ++nt) {
                uint2 b = Bq[(ks * 16 + wc * 4 + nt) * 32 + lane];
#pragma unroll
                for (int mt = 0; mt < 4; ++mt) mma_f16(C[mt][nt], a[mt], b);
            }
        }
    }

    // Epilogue: write fp16 sims pair-blocked [i*128+j][r][w].
    unsigned jj[4], ww[4];
#pragma unroll
    for (int nt = 0; nt < 4; ++nt) {
        unsigned Cc = nb * 128 + (wc * 4 + nt) * 8 + 2 * tig;  // even
        jj[nt] = Cc / 50u;
        ww[nt] = Cc - jj[nt] * 50u;                            // even
    }
#pragma unroll
    for (int mt = 0; mt < 4; ++mt) {
#pragma unroll
        for (int hh = 0; hh < 2; ++hh) {
            unsigned R = mb * 128 + (wr * 4 + mt) * 16 + gid + 8 * hh;
            unsigned ii = R / 36u;
            unsigned r = R - ii * 36u;
            unsigned rowbase = (ii << 7) * PAIR_ELEMS + r * 50u;
#pragma unroll
            for (int nt = 0; nt < 4; ++nt) {
                uint32_t pk = pack_h2(C[mt][nt][2 * hh], C[mt][nt][2 * hh + 1]);
                size_t idx = rowbase + jj[nt] * PAIR_ELEMS + ww[nt];
                *reinterpret_cast<uint32_t*>(g_sims + idx) = pk;
            }
        }
    }
}

// ---------------------------------------------------------------------------
// Kernel 3: Sinkhorn. Warp-private pair; 8 pairs per 256-thr CTA.
// Loops bounded by runtime Ri/Wj. Masked K entries stored as exact 0.
// ---------------------------------------------------------------------------
__global__ __launch_bounds__(256, 3)
void sinkhorn_kernel(const int* __restrict__ img_lens,
                     const int* __restrict__ cap_lens,
                     float* __restrict__ out) {
    extern __shared__ float smem[];
    const int tid = threadIdx.x;
    const int lane = tid & 31;
    const int wid = tid >> 5;
    const int pid = blockIdx.x * 8 + wid;
    const int i = pid >> 7;
    const int j = pid & 127;
    const int Ri = img_lens[i];
    const int Wj = cap_lens[j];

    const uint32_t* S32 = reinterpret_cast<const uint32_t*>(
        g_sims + (size_t)pid * PAIR_ELEMS);          // row stride 25 u32
    float* Kp = smem + wid * KS_STRIDE;              // [36][58]
    float* alp = smem + AL_OFF + wid * RR;
    float* bet = smem + BE_OFF + wid * BET_STRIDE;

    const int nh = (Wj + 1) >> 1;

    // load + exp + K store (masked entries -> 0); total sum
    float tsum = 0.0f;
    for (int r = lane; r < Ri; r += 32) {
        const uint32_t* row = S32 + r * 25;
        float* kr = Kp + r * KW;
        for (int t = 0; t < nh; ++t) {
            __half2 hv = *reinterpret_cast<const __half2*>(&row[t]);
            float2 f = __half22float2(hv);
            float k0 = __expf(20.0f * f.x - 20.0f);
            float k1 = (2 * t + 1 < Wj) ? __expf(20.0f * f.y - 20.0f) : 0.0f;
            *reinterpret_cast<float2*>(kr + 2 * t) = make_float2(k0, k1);
            tsum += k0 + k1;
        }
    }
#pragma unroll
    for (int o = 16; o > 0; o >>= 1) tsum += __shfl_xor_sync(0xffffffffu, tsum, o);
    float alpha0 = 1.0f / (tsum + EPSV);

    for (int r = lane; r < Ri; r += 32) alp[r] = alpha0;
    for (int w = lane; w < Wj + (Wj & 1); w += 32)
        bet[w] = (w < Wj) ? 1.0f : 0.0f;
    const float rm = 1.0f / (float)Ri;
    const float cm = 1.0f / (float)Wj;
    __syncwarp();

#pragma unroll
    for (int it = 0; it < 3; ++it) {
        for (int r = lane; r < Ri; r += 32) {
            const float2* kr = reinterpret_cast<const float2*>(Kp + r * KW);
            const float2* b2 = reinterpret_cast<const float2*>(bet);
            float dot = 0.0f;
            for (int t = 0; t < nh; ++t) {
                float2 kv = kr[t], bv = b2[t];
                dot += kv.x * bv.x;
                dot += kv.y * bv.y;
            }
            float a = alp[r];
            alp[r] = a * (rm / (a * dot + EPSV));
        }
        __syncwarp();
        for (int w = lane; w < Wj; w += 32) {
            float dot = 0.0f;
            for (int r = 0; r < Ri; ++r) dot += Kp[r * KW + w] * alp[r];
            float b = bet[w];
            bet[w] = b * (cm / (b * dot + EPSV));
        }
        __syncwarp();
    }

    // final: sum s * K * alp * bet  (K==0 where masked, so no guards needed)
    float acc = 0.0f;
    for (int r = lane; r < Ri; r += 32) {
        const uint32_t* row = S32 + r * 25;
        const float2* kr = reinterpret_cast<const float2*>(Kp + r * KW);
        const float2* b2 = reinterpret_cast<const float2*>(bet);
        float racc = 0.0f;
        for (int t = 0; t < nh; ++t) {
            __half2 hv = *reinterpret_cast<const __half2*>(&row[t]);
            float2 f = __half22float2(hv);
            float2 kv = kr[t], bv = b2[t];
            racc += f.x * kv.x * bv.x;
            racc += f.y * kv.y * bv.y;
        }
        acc += alp[r] * racc;
    }
#pragma unroll
    for (int o = 16; o > 0; o >>= 1) acc += __shfl_xor_sync(0xffffffffu, acc, o);
    if (lane == 0) out[i * BT + j] = acc;
}

// ---------------------------------------------------------------------------
extern "C" void kernel_launch(void* const* d_in, const int* in_sizes, int n_in,
                              void* d_out, int out_size) {
    const float* imgs = (const float*)d_in[0];
    const float* caps = (const float*)d_in[1];
    const int* img_lens = (const int*)d_in[2];
    const int* cap_lens = (const int*)d_in[3];
    float* out = (float*)d_out;

    cudaFuncSetAttribute(norm_kernel,
                         cudaFuncAttributeMaxDynamicSharedMemorySize, NORM_SMEM);
    cudaFuncSetAttribute(gemm_kernel,
                         cudaFuncAttributeMaxDynamicSharedMemorySize, GEMM_SMEM);
    cudaFuncSetAttribute(sinkhorn_kernel,
                         cudaFuncAttributeMaxDynamicSharedMemorySize, SINK_SMEM);

    norm_kernel<<<(MB + NB) * 4, 256, NORM_SMEM>>>(imgs, caps);
    gemm_kernel<<<dim3(NB, MB), 256, GEMM_SMEM>>>();
    sinkhorn_kernel<<<(BI * BT) / 8, 256, SINK_SMEM>>>(img_lens, cap_lens, out);
}

// round 16
// speedup vs baseline: 1.3743x; 1.1317x over previous
#include <cuda_runtime.h>
#include <cuda_fp16.h>
#include <cstdint>

#define BI 128
#define BT 128
#define RR 36
#define WW 50
#define DD 256
#define EPSV 1e-6f

#define MROWS 4608           // worst-case compacted rows (36*128)
#define NCOLS 6400           // worst-case compacted cols (50*128)
#define MB 36                // worst-case M blocks of 128
#define NB 50                // worst-case N blocks of 128
#define NCHUNK 8
#define NBUF 4

// Fragment layouts in gmem (u32 = f16x2), per 128-row/col block:
// g_aq[mb][ksg][mt(8)][lane(32)][q(4)]  -> 16384 u32 per mb
// g_bq[nb][ksg][nt(16)][lane(32)][p(2)] -> 16384 u32 per nb
#define ABLK_U32 16384
#define BBLK_U32 16384
#define CHUNK_U32 2048
#define GBUF_U32 4096
#define GBUF_BYTES 16384
#define GEMM_SMEM (NBUF * GBUF_BYTES)   // 65536

// sims: pair-blocked fp16 [pair(16384)][r(36)][w(50)]
#define PAIR_ELEMS 1800

// Sinkhorn smem (per 8-warp CTA)
#define KW 58
#define KS_STRIDE (RR * KW)             // 2088
#define AL_OFF (8 * KS_STRIDE)
#define BE_OFF (AL_OFF + 8 * RR)
#define BET_STRIDE 52
#define SINK_SMEM ((BE_OFF + 8 * BET_STRIDE) * 4)   // 69632

#define NORM_SMEM 16384

__device__ uint32_t g_aq[MB * ABLK_U32];
__device__ uint32_t g_bq[NB * BBLK_U32];
__device__ uint16_t g_sims[(size_t)BI * BT * PAIR_ELEMS];  // zero-init; unwritten slots stay 0
__device__ int g_dims[2];                 // nMB, nNB (active block counts)
__device__ int g_rowmap[MROWS];           // compacted row -> (i<<6)|r, or -1
__device__ int g_colmap[NCOLS + 2];       // compacted col -> (j<<6)|w, or -1

__device__ __forceinline__ uint32_t pack_h2(float lo, float hi) {
    uint32_t r;
    asm("cvt.rn.f16x2.f32 %0, %1, %2;" : "=r"(r) : "f"(hi), "f"(lo));
    return r;
}
__device__ __forceinline__ uint16_t f2h(float x) {
    uint16_t r;
    asm("cvt.rn.f16.f32 %0, %1;" : "=h"(r) : "f"(x));
    return r;
}
__device__ __forceinline__ void cp16(uint32_t dst, const void* src) {
    asm volatile("cp.async.cg.shared.global [%0], [%1], 16;\n"
                 :: "r"(dst), "l"(src));
}

// ---------------------------------------------------------------------------
// Kernel 0: build compaction maps + active block counts. One block.
// ---------------------------------------------------------------------------
__global__ void prep_kernel(const int* __restrict__ img_lens,
                            const int* __restrict__ cap_lens) {
    __shared__ int offA[BI], offB[BT];
    const int tid = threadIdx.x;
    if (tid == 0) {
        int s = 0;
        for (int i = 0; i < BI; ++i) { offA[i] = s; s += img_lens[i]; }
        g_dims[0] = (s + 127) >> 7;
        int t = 0;
        for (int j = 0; j < BT; ++j) { offB[j] = t; t += cap_lens[j]; }
        g_dims[1] = (t + 127) >> 7;
    }
    __syncthreads();
    for (int x = tid; x < MROWS; x += 256) g_rowmap[x] = -1;
    for (int x = tid; x < NCOLS + 2; x += 256) g_colmap[x] = -1;
    __syncthreads();
    if (tid < BI) {
        int o = offA[tid], n = img_lens[tid];
        for (int r = 0; r < n; ++r) g_rowmap[o + r] = (tid << 6) | r;
    }
    if (tid < BT) {
        int o = offB[tid], n = cap_lens[tid];
        for (int w = 0; w < n; ++w) g_colmap[o + w] = (tid << 6) | w;
    }
}

// ---------------------------------------------------------------------------
// Kernel 1: L2-normalize + fp16 + fragment prebake over COMPACTED rows.
// 4 CTAs per 128-row block; sentinel rows -> zero fragments.
// ---------------------------------------------------------------------------
__global__ __launch_bounds__(256)
void norm_kernel(const float* __restrict__ imgs,
                 const float* __restrict__ caps) {
    extern __shared__ uint32_t sm[];
    const int bq = blockIdx.x;
    const int b = bq >> 2;
    const int q = bq & 3;
    const int tid = threadIdx.x;
    const int lane = tid & 31;
    const int wrp = tid >> 5;
    const int ksg = lane >> 1;
    const int sel = lane & 1;

    const bool isA = (b < MB);
    const int blk = isA ? b : b - MB;

#pragma unroll
    for (int it = 0; it < 4; ++it) {
        const int rr = q * 32 + wrp + 8 * it;
        const int m = isA ? g_rowmap[blk * 128 + rr]
                          : g_colmap[blk * 128 + rr];
        float v[8];
        if (m >= 0) {   // warp-uniform (rr uniform per warp)
            const int src_row = isA ? ((m >> 6) * RR + (m & 63))
                                    : ((m >> 6) * WW + (m & 63));
            const float* base = isA ? imgs : caps;
            const float4* s4 = reinterpret_cast<const float4*>(
                base + (size_t)src_row * DD);
            float4 v0 = s4[2 * lane], v1 = s4[2 * lane + 1];
            float ss = v0.x * v0.x + v0.y * v0.y + v0.z * v0.z + v0.w * v0.w
                     + v1.x * v1.x + v1.y * v1.y + v1.z * v1.z + v1.w * v1.w;
#pragma unroll
            for (int o = 16; o > 0; o >>= 1)
                ss += __shfl_xor_sync(0xffffffffu, ss, o);
            float inv = 1.0f / fmaxf(sqrtf(ss), 1e-8f);
            v[0] = v0.x * inv; v[1] = v0.y * inv;
            v[2] = v0.z * inv; v[3] = v0.w * inv;
            v[4] = v1.x * inv; v[5] = v1.y * inv;
            v[6] = v1.z * inv; v[7] = v1.w * inv;
        } else {
#pragma unroll
            for (int y = 0; y < 8; ++y) v[y] = 0.0f;
        }

        if (isA) {
            int mtl = ((rr >> 4) & 1);
            int x = rr & 15, g = x & 7, hi = x >> 3;
#pragma unroll
            for (int t = 0; t < 4; ++t)
                sm[((ksg * 2 + mtl) * 32 + g * 4 + t) * 4 + sel * 2 + hi] =
                    pack_h2(v[2 * t], v[2 * t + 1]);
        } else {
            int ntl = (rr >> 3) & 3;
            int g = rr & 7;
#pragma unroll
            for (int t = 0; t < 4; ++t)
                sm[((ksg * 4 + ntl) * 32 + g * 4 + t) * 2 + sel] =
                    pack_h2(v[2 * t], v[2 * t + 1]);
        }
    }
    __syncthreads();

    const uint4* s4 = reinterpret_cast<const uint4*>(sm);
    if (isA) {
        uint4* dst = reinterpret_cast<uint4*>(g_aq + (size_t)blk * ABLK_U32);
#pragma unroll
        for (int s = 0; s < 4; ++s) {
            int idx = tid + s * 256;
            int kk = idx >> 6, off = idx & 63;
            dst[(kk * 8 + 2 * q) * 32 + off] = s4[idx];
        }
    } else {
        uint4* dst = reinterpret_cast<uint4*>(g_bq + (size_t)blk * BBLK_U32);
#pragma unroll
        for (int s = 0; s < 4; ++s) {
            int idx = tid + s * 256;
            int kk = idx >> 6, off = idx & 63;
            dst[(kk * 16 + 4 * q) * 16 + off] = s4[idx];
        }
    }
}

// ---------------------------------------------------------------------------
// m16n8k16 fp16 mma, fp32 accumulate
// ---------------------------------------------------------------------------
__device__ __forceinline__ void mma_f16(float* c, const uint4& a, const uint2& b) {
    asm volatile(
        "mma.sync.aligned.m16n8k16.row.col.f32.f16.f16.f32 "
        "{%0,%1,%2,%3}, {%4,%5,%6,%7}, {%8,%9}, {%0,%1,%2,%3};\n"
        : "+f"(c[0]), "+f"(c[1]), "+f"(c[2]), "+f"(c[3])
        : "r"(a.x), "r"(a.y), "r"(a.z), "r"(a.w), "r"(b.x), "r"(b.y));
}

// ---------------------------------------------------------------------------
// Kernel 2: compacted GEMM. Static grid (NB, MB); CTAs beyond active block
// counts exit. Epilogue scatters through row/col maps (per-fp16 stores).
// ---------------------------------------------------------------------------
__global__ __launch_bounds__(256, 2)
void gemm_kernel() {
    const int nb = blockIdx.x;
    const int mb = blockIdx.y;
    if (mb >= g_dims[0] || nb >= g_dims[1]) return;

    extern __shared__ uint32_t sm32[];
    const int tid = threadIdx.x;
    const int lane = tid & 31;
    const int wid = tid >> 5;
    const int gid = lane >> 2;
    const int tig = lane & 3;
    const int wr = wid >> 2;
    const int wc = wid & 3;

    uint32_t sb;
    asm("{ .reg .u64 t; cvta.to.shared.u64 t, %1; cvt.u32.u64 %0, t; }"
        : "=r"(sb) : "l"(sm32));

    const uint32_t* srcA = g_aq + (size_t)mb * ABLK_U32 + tid * 4;
    const uint32_t* srcB = g_bq + (size_t)nb * BBLK_U32 + tid * 4;
    const uint32_t dA = (uint32_t)(tid * 16);
    const uint32_t dB = (uint32_t)(8192 + tid * 16);

    float C[4][4][4];
#pragma unroll
    for (int mt = 0; mt < 4; ++mt)
#pragma unroll
        for (int nt = 0; nt < 4; ++nt)
#pragma unroll
            for (int c = 0; c < 4; ++c) C[mt][nt][c] = 0.0f;

    auto do_stage = [&](int s) {
        uint32_t bufb = sb + (uint32_t)(s & (NBUF - 1)) * GBUF_BYTES;
        cp16(bufb + dA, srcA);
        cp16(bufb + dA + 4096, srcA + 1024);
        cp16(bufb + dB, srcB);
        cp16(bufb + dB + 4096, srcB + 1024);
        srcA += CHUNK_U32;
        srcB += CHUNK_U32;
        asm volatile("cp.async.commit_group;" ::: "memory");
    };

    do_stage(0);
    do_stage(1);

    for (int ch = 0; ch < NCHUNK; ++ch) {
        if (ch < NCHUNK - 1) {
            asm volatile("cp.async.wait_group 1;" ::: "memory");
        } else {
            asm volatile("cp.async.wait_group 0;" ::: "memory");
        }
        __syncthreads();
        if (ch + 2 < NCHUNK) do_stage(ch + 2);

        const uint32_t* buf = sm32 + (ch & (NBUF - 1)) * GBUF_U32;
        const uint4* Aq = reinterpret_cast<const uint4*>(buf);
        const uint2* Bq = reinterpret_cast<const uint2*>(buf + 2048);
#pragma unroll
        for (int ks = 0; ks < 2; ++ks) {
            uint4 a[4];
#pragma unroll
            for (int mt = 0; mt < 4; ++mt)
                a[mt] = Aq[(ks * 8 + wr * 4 + mt) * 32 + lane];
#pragma unroll
            for (int nt = 0; nt < 4; ++nt) {
                uint2 b = Bq[(ks * 16 + wc * 4 + nt) * 32 + lane];
#pragma unroll
                for (int mt = 0; mt < 4; ++mt) mma_f16(C[mt][nt], a[mt], b);
            }
        }
    }

    // Epilogue: map compacted (row, col) -> (i,r),(j,w); store fp16 elements.
    int c0[4], c1[4];
#pragma unroll
    for (int nt = 0; nt < 4; ++nt) {
        int Cc = nb * 128 + (wc * 4 + nt) * 8 + 2 * tig;
        c0[nt] = g_colmap[Cc];
        c1[nt] = g_colmap[Cc + 1];
    }
#pragma unroll
    for (int mt = 0; mt < 4; ++mt) {
#pragma unroll
        for (int hh = 0; hh < 2; ++hh) {
            int R = mb * 128 + (wr * 4 + mt) * 16 + gid + 8 * hh;
            int m = g_rowmap[R];
            if (m >= 0) {
                size_t base = ((size_t)((m >> 6) << 7)) * PAIR_ELEMS
                            + (size_t)(m & 63) * 50;
#pragma unroll
                for (int nt = 0; nt < 4; ++nt) {
                    if (c0[nt] >= 0)
                        g_sims[base + (size_t)(c0[nt] >> 6) * PAIR_ELEMS
                               + (c0[nt] & 63)] = f2h(C[mt][nt][2 * hh]);
                    if (c1[nt] >= 0)
                        g_sims[base + (size_t)(c1[nt] >> 6) * PAIR_ELEMS
                               + (c1[nt] & 63)] = f2h(C[mt][nt][2 * hh + 1]);
                }
            }
        }
    }
}

// ---------------------------------------------------------------------------
// Kernel 3: Sinkhorn. Warp-private pair; 8 pairs per 256-thr CTA.
// Unwritten sims slots are 0 (zero-init device global) -> harmless.
// ---------------------------------------------------------------------------
__global__ __launch_bounds__(256, 3)
void sinkhorn_kernel(const int* __restrict__ img_lens,
                     const int* __restrict__ cap_lens,
                     float* __restrict__ out) {
    extern __shared__ float smem[];
    const int tid = threadIdx.x;
    const int lane = tid & 31;
    const int wid = tid >> 5;
    const int pid = blockIdx.x * 8 + wid;
    const int i = pid >> 7;
    const int j = pid & 127;
    const int Ri = img_lens[i];
    const int Wj = cap_lens[j];

    const uint32_t* S32 = reinterpret_cast<const uint32_t*>(
        g_sims + (size_t)pid * PAIR_ELEMS);
    float* Kp = smem + wid * KS_STRIDE;
    float* alp = smem + AL_OFF + wid * RR;
    float* bet = smem + BE_OFF + wid * BET_STRIDE;

    const int nh = (Wj + 1) >> 1;

    float tsum = 0.0f;
    for (int r = lane; r < Ri; r += 32) {
        const uint32_t* row = S32 + r * 25;
        float* kr = Kp + r * KW;
        for (int t = 0; t < nh; ++t) {
            __half2 hv = *reinterpret_cast<const __half2*>(&row[t]);
            float2 f = __half22float2(hv);
            float k0 = __expf(20.0f * f.x - 20.0f);
            float k1 = (2 * t + 1 < Wj) ? __expf(20.0f * f.y - 20.0f) : 0.0f;
            *reinterpret_cast<float2*>(kr + 2 * t) = make_float2(k0, k1);
            tsum += k0 + k1;
        }
    }
#pragma unroll
    for (int o = 16; o > 0; o >>= 1) tsum += __shfl_xor_sync(0xffffffffu, tsum, o);
    float alpha0 = 1.0f / (tsum + EPSV);

    for (int r = lane; r < Ri; r += 32) alp[r] = alpha0;
    for (int w = lane; w < Wj + (Wj & 1); w += 32)
        bet[w] = (w < Wj) ? 1.0f : 0.0f;
    const float rm = 1.0f / (float)Ri;
    const float cm = 1.0f / (float)Wj;
    __syncwarp();

#pragma unroll
    for (int it = 0; it < 3; ++it) {
        for (int r = lane; r < Ri; r += 32) {
            const float2* kr = reinterpret_cast<const float2*>(Kp + r * KW);
            const float2* b2 = reinterpret_cast<const float2*>(bet);
            float dot = 0.0f;
            for (int t = 0; t < nh; ++t) {
                float2 kv = kr[t], bv = b2[t];
                dot += kv.x * bv.x;
                dot += kv.y * bv.y;
            }
            float a = alp[r];
            alp[r] = a * (rm / (a * dot + EPSV));
        }
        __syncwarp();
        for (int w = lane; w < Wj; w += 32) {
            float dot = 0.0f;
            for (int r = 0; r < Ri; ++r) dot += Kp[r * KW + w] * alp[r];
            float b = bet[w];
            bet[w] = b * (cm / (b * dot + EPSV));
        }
        __syncwarp();
    }

    float acc = 0.0f;
    for (int r = lane; r < Ri; r += 32) {
        const uint32_t* row = S32 + r * 25;
        const float2* kr = reinterpret_cast<const float2*>(Kp + r * KW);
        const float2* b2 = reinterpret_cast<const float2*>(bet);
        float racc = 0.0f;
        for (int t = 0; t < nh; ++t) {
            __half2 hv = *reinterpret_cast<const __half2*>(&row[t]);
            float2 f = __half22float2(hv);
            float2 kv = kr[t], bv = b2[t];
            racc += f.x * kv.x * bv.x;
            racc += f.y * kv.y * bv.y;
        }
        acc += alp[r] * racc;
    }
#pragma unroll
    for (int o = 16; o > 0; o >>= 1) acc += __shfl_xor_sync(0xffffffffu, acc, o);
    if (lane == 0) out[i * BT + j] = acc;
}

// ---------------------------------------------------------------------------
extern "C" void kernel_launch(void* const* d_in, const int* in_sizes, int n_in,
                              void* d_out, int out_size) {
    const float* imgs = (const float*)d_in[0];
    const float* caps = (const float*)d_in[1];
    const int* img_lens = (const int*)d_in[2];
    const int* cap_lens = (const int*)d_in[3];
    float* out = (float*)d_out;

    cudaFuncSetAttribute(norm_kernel,
                         cudaFuncAttributeMaxDynamicSharedMemorySize, NORM_SMEM);
    cudaFuncSetAttribute(gemm_kernel,
                         cudaFuncAttributeMaxDynamicSharedMemorySize, GEMM_SMEM);
    cudaFuncSetAttribute(sinkhorn_kernel,
                         cudaFuncAttributeMaxDynamicSharedMemorySize, SINK_SMEM);

    prep_kernel<<<1, 256>>>(img_lens, cap_lens);
    norm_kernel<<<(MB + NB) * 4, 256, NORM_SMEM>>>(imgs, caps);
    gemm_kernel<<<dim3(NB, MB), 256, GEMM_SMEM>>>();
    sinkhorn_kernel<<<(BI * BT) / 8, 256, SINK_SMEM>>>(img_lens, cap_lens, out);
}